// round 6
// baseline (speedup 1.0000x reference)
#include <cuda_runtime.h>
#include <cuda_fp16.h>
#include <math.h>
#include <float.h>

// ---------------------------------------------------------------------------
// MultiBoxLoss (SSD) fused loss.  B=32, P=8732, C=81.
//   out[0] = loss_c / N, out[1] = loss_l / N
// Warp-specialized pipeline: producer warps stream conf tiles (f32 global ->
// fp16 smem, 2 stages) while consumer warps compute per-prior nll from smem.
// nll = lse - tgt_logit is both the CE term and the hard-negative rank key.
// Common case (num_neg >= #negatives): loss_c = sum of ALL nll.
// Rare case: exact top-k via radix select (tie-order invariant for a sum).
// ---------------------------------------------------------------------------

#define BATCH    32
#define PRIORS   8732
#define CLASSES  81
#define TPB      256                               // 128 producers + 128 consumers
#define CONS     128
#define TILES_PER_BATCH ((PRIORS + CONS - 1) / CONS)  // 69
#define NTILES   (TILES_PER_BATCH * BATCH)         // 2208
#define GRID_MAIN 444                              // ~5 contiguous tiles/block
#define FULLMASK 0xFFFFFFFFu

#define BAR_FULL(s)   (1 + (s))
#define BAR_EMPTY(s)  (3 + (s))

#define BARS(id)  asm volatile("bar.sync %0, 256;"   :: "r"(id))
#define BARA(id)  asm volatile("bar.arrive %0, 256;" :: "r"(id))
#define BARSC()   asm volatile("bar.sync 5, 128;" ::)

// Device-global scratch; statically zero-init. The fused finalizer resets
// everything at the end of each call -> graph replays are deterministic.
__device__ double   g_sum_all[BATCH];
__device__ double   g_sum_pos[BATCH];
__device__ double   g_sum_loc[BATCH];
__device__ int      g_num_pos[BATCH];
__device__ int      g_flag64 = 1;          // 1 -> conf_t is int64
__device__ unsigned g_done   = 0;
__device__ float    g_vrank[BATCH * PRIORS];

// Detect int64 vs int32 labels reading ONLY the first 16384 int32 words
// (in-bounds under either layout). int64 labels in [0,81) -> odd words zero.
__global__ void k_detect(const int2* __restrict__ p) {
    int bad = 0;
    for (int i = blockIdx.x * blockDim.x + threadIdx.x; i < 8192;
         i += gridDim.x * blockDim.x)
        bad |= p[i].y;
    if (__syncthreads_or(bad) && threadIdx.x == 0) g_flag64 = 0;
}

__global__ void __launch_bounds__(TPB)
k_main(const float* __restrict__ conf,
       const float4* __restrict__ loc,
       const void*  __restrict__ ct,
       const float4* __restrict__ loct,
       float* __restrict__ out, int out_size) {
    __shared__ __align__(16) __half s_buf[2][CONS * CLASSES];  // 2 x 20,736 B
    __shared__ float    s_f[4 * 3];
    __shared__ int      s_i[4];
    __shared__ unsigned s_last;
    __shared__ unsigned sh_prefix, sh_rare;
    __shared__ int      sh_k;
    __shared__ double   sh_lc, sh_ll;
    __shared__ long long sh_n;

    // finalizer scratch aliases stage 0 (only used after pipeline is done)
    double*   dred = (double*)&s_buf[0][0];        // 256 * 8B
    unsigned* hist = (unsigned*)(dred + 256);      // 256 * 4B

    const int tid  = threadIdx.x;
    const int bid  = blockIdx.x;
    const int t0   = (bid * NTILES) / GRID_MAIN;
    const int t1   = ((bid + 1) * NTILES) / GRID_MAIN;
    const int nt   = t1 - t0;                      // 4 or 5
    const bool is64 = (g_flag64 != 0);

    if (tid < CONS) {
        // ------------------------------ PRODUCER ---------------------------
        const int ptid = tid;
        for (int i = t0; i < t1; i++) {
            const int s  = (i - t0) & 1;
            if (i - t0 >= 2) BARS(BAR_EMPTY(s));
            const int b  = i / TILES_PER_BATCH;
            const int tl = i % TILES_PER_BATCH;
            const int p0 = tl * CONS;
            const int np = min(CONS, PRIORS - p0);
            const long long g0 = (long long)b * PRIORS + p0;

            const float4* src4 = (const float4*)(conf + g0 * CLASSES);
            __half2* dst2 = (__half2*)&s_buf[s][0];
            const int n4 = (np * CLASSES) >> 2;    // always divisible by 4
            #pragma unroll 4
            for (int j = ptid; j < n4; j += CONS) {
                const float4 v = src4[j];
                dst2[2 * j]     = __floats2half2_rn(v.x, v.y);
                dst2[2 * j + 1] = __floats2half2_rn(v.z, v.w);
            }
            __threadfence_block();
            BARA(BAR_FULL(s));
        }
        // drain the consumer's final EMPTY arrivals so no barrier exits with
        // partial count (consumer reaches those arrives unconditionally).
        if (nt >= 2) BARS(BAR_EMPTY((nt - 2) & 1));
        if (nt >= 1) BARS(BAR_EMPTY((nt - 1) & 1));
    } else {
        // ------------------------------ CONSUMER ---------------------------
        const int ctid = tid - CONS;
        const int lane = tid & 31;
        const int cw   = (tid >> 5) - 4;           // consumer warp 0..3
        float acc_all = 0.f, acc_pos = 0.f, acc_loc = 0.f;
        int   acc_cnt = 0, cur_b = -1;

        for (int i = t0; i < t1; i++) {
            const int s  = (i - t0) & 1;
            const int b  = i / TILES_PER_BATCH;
            const int tl = i % TILES_PER_BATCH;
            const int p0 = tl * CONS;
            const int np = min(CONS, PRIORS - p0);
            const long long g0 = (long long)b * PRIORS + p0;

            if (b != cur_b) {                      // flush previous batch
                if (cur_b >= 0) {
                    float a = acc_all, pp = acc_pos, lcv = acc_loc; int nc = acc_cnt;
                    #pragma unroll
                    for (int o = 16; o > 0; o >>= 1) {
                        a  += __shfl_down_sync(FULLMASK, a,  o);
                        pp += __shfl_down_sync(FULLMASK, pp, o);
                        lcv+= __shfl_down_sync(FULLMASK, lcv,o);
                        nc += __shfl_down_sync(FULLMASK, nc, o);
                    }
                    if (lane == 0) { s_f[cw] = a; s_f[4+cw] = pp; s_f[8+cw] = lcv; s_i[cw] = nc; }
                    BARSC();
                    if (ctid == 0) {
                        atomicAdd(&g_sum_all[cur_b], (double)(s_f[0]+s_f[1]+s_f[2]+s_f[3]));
                        atomicAdd(&g_sum_pos[cur_b], (double)(s_f[4]+s_f[5]+s_f[6]+s_f[7]));
                        atomicAdd(&g_sum_loc[cur_b], (double)(s_f[8]+s_f[9]+s_f[10]+s_f[11]));
                        atomicAdd(&g_num_pos[cur_b], s_i[0]+s_i[1]+s_i[2]+s_i[3]);
                    }
                    BARSC();
                    acc_all = acc_pos = acc_loc = 0.f; acc_cnt = 0;
                }
                cur_b = b;
            }

            // label load (global, independent of smem stage)
            int t = 0;
            const bool active = (ctid < np);
            if (active) {
                t = is64 ? (int)((const long long*)ct)[g0 + ctid]
                         : ((const int*)ct)[g0 + ctid];
            }

            BARS(BAR_FULL(s));
            if (active) {
                const __half* r = &s_buf[s][ctid * CLASSES];
                float e0 = 0.f, e1 = 0.f, e2 = 0.f, e3 = 0.f;
                #pragma unroll
                for (int k = 0; k < 80; k += 4) {
                    e0 += __expf(__half2float(r[k]));
                    e1 += __expf(__half2float(r[k + 1]));
                    e2 += __expf(__half2float(r[k + 2]));
                    e3 += __expf(__half2float(r[k + 3]));
                }
                const float sum = ((e0 + e1) + (e2 + e3)) + __expf(__half2float(r[80]));
                const float nll = __logf(sum) - __half2float(r[t]);
                const bool  pos = (t > 0);
                g_vrank[g0 + ctid] = pos ? 0.f : nll;
                acc_all += nll;
                if (pos) {
                    acc_pos += nll; acc_cnt++;
                    const float4 d4 = loc[g0 + ctid], t4 = loct[g0 + ctid];
                    float dx = d4.x - t4.x, dy = d4.y - t4.y;
                    float dz = d4.z - t4.z, dw = d4.w - t4.w;
                    float ax = fabsf(dx), ay = fabsf(dy), az = fabsf(dz), aw = fabsf(dw);
                    acc_loc += ((ax < 1.f) ? 0.5f * dx * dx : ax - 0.5f)
                             + ((ay < 1.f) ? 0.5f * dy * dy : ay - 0.5f)
                             + ((az < 1.f) ? 0.5f * dz * dz : az - 0.5f)
                             + ((aw < 1.f) ? 0.5f * dw * dw : aw - 0.5f);
                }
            }
            BARA(BAR_EMPTY(s));
        }

        if (cur_b >= 0) {                          // final flush
            float a = acc_all, pp = acc_pos, lcv = acc_loc; int nc = acc_cnt;
            #pragma unroll
            for (int o = 16; o > 0; o >>= 1) {
                a  += __shfl_down_sync(FULLMASK, a,  o);
                pp += __shfl_down_sync(FULLMASK, pp, o);
                lcv+= __shfl_down_sync(FULLMASK, lcv,o);
                nc += __shfl_down_sync(FULLMASK, nc, o);
            }
            if (lane == 0) { s_f[cw] = a; s_f[4+cw] = pp; s_f[8+cw] = lcv; s_i[cw] = nc; }
            BARSC();
            if (ctid == 0) {
                atomicAdd(&g_sum_all[cur_b], (double)(s_f[0]+s_f[1]+s_f[2]+s_f[3]));
                atomicAdd(&g_sum_pos[cur_b], (double)(s_f[4]+s_f[5]+s_f[6]+s_f[7]));
                atomicAdd(&g_sum_loc[cur_b], (double)(s_f[8]+s_f[9]+s_f[10]+s_f[11]));
                atomicAdd(&g_num_pos[cur_b], s_i[0]+s_i[1]+s_i[2]+s_i[3]);
            }
            BARSC();
        }
    }

    __syncthreads();
    if (tid == 0) {
        __threadfence();
        s_last = atomicAdd(&g_done, 1u);
    }
    __syncthreads();
    if (s_last != (unsigned)(gridDim.x - 1)) return;

    // ======================= fused finalizer (last block) ===================
    __threadfence();
    if (tid < 32) {
        const int    npb  = ((volatile int*)g_num_pos)[tid];
        const double sall = ((volatile double*)g_sum_all)[tid];
        const double sloc = ((volatile double*)g_sum_loc)[tid];
        const long long nn = min((long long)3 * npb, (long long)(PRIORS - 1));
        const bool rare = (nn < (long long)(PRIORS - npb));
        const unsigned rm = __ballot_sync(FULLMASK, rare);
        double c = rare ? 0.0 : sall;
        double l = sloc;
        int    n = npb;
        #pragma unroll
        for (int o = 16; o > 0; o >>= 1) {
            c += __shfl_down_sync(FULLMASK, c, o);
            l += __shfl_down_sync(FULLMASK, l, o);
            n += __shfl_down_sync(FULLMASK, n, o);
        }
        if (tid == 0) { sh_lc = c; sh_ll = l; sh_n = n; sh_rare = rm; }
    }
    __syncthreads();

    double loss_c = sh_lc;
    unsigned rmask = sh_rare;
    // rare path: exact top-k radix select per flagged batch (expected none)
    while (rmask) {
        const int rb = __ffs(rmask) - 1;
        rmask &= rmask - 1;
        const int npb = ((volatile int*)g_num_pos)[rb];
        int kk = (int)min((long long)3 * npb, (long long)(PRIORS - 1));
        const float* v = g_vrank + (long long)rb * PRIORS;
        unsigned prefix = 0;
        for (int shift = 24; shift >= 0; shift -= 8) {
            for (int i = tid; i < 256; i += TPB) hist[i] = 0;
            __syncthreads();
            const unsigned mask_hi =
                (shift == 24) ? 0u : (0xFFFFFFFFu << (shift + 8));
            for (int i = tid; i < PRIORS; i += TPB) {
                const unsigned bits = __float_as_uint(v[i]);
                if ((bits & mask_hi) == prefix)
                    atomicAdd(&hist[(bits >> shift) & 255], 1u);
            }
            __syncthreads();
            if (tid == 0) {
                int acc = 0, bin = 255;
                for (; bin > 0; --bin) {
                    if (acc + (int)hist[bin] >= kk) break;
                    acc += (int)hist[bin];
                }
                sh_prefix = prefix | ((unsigned)bin << shift);
                sh_k      = kk - acc;
            }
            __syncthreads();
            prefix = sh_prefix; kk = sh_k;
            __syncthreads();
        }
        double local = 0.0;
        for (int i = tid; i < PRIORS; i += TPB) {
            const unsigned bits = __float_as_uint(v[i]);
            if (bits > prefix) local += (double)v[i];
        }
        dred[tid] = local;
        __syncthreads();
        for (int st = TPB / 2; st > 0; st >>= 1) {
            if (tid < st) dred[tid] += dred[tid + st];
            __syncthreads();
        }
        if (tid == 0) {
            loss_c += ((volatile double*)g_sum_pos)[rb] + dred[0] +
                      (double)kk * (double)__uint_as_float(prefix);
        }
        __syncthreads();
    }

    if (tid == 0) {
        const double N = (double)sh_n;
        if (out_size >= 1) out[0] = (float)(loss_c / N);
        if (out_size >= 2) out[1] = (float)(sh_ll / N);
    }

    // reset globals for the next graph replay
    if (tid < BATCH) {
        g_sum_all[tid] = 0.0; g_sum_pos[tid] = 0.0;
        g_sum_loc[tid] = 0.0; g_num_pos[tid] = 0;
    }
    if (tid == 0) { g_flag64 = 1; g_done = 0; }
}

extern "C" void kernel_launch(void* const* d_in, const int* in_sizes, int n_in,
                              void* d_out, int out_size) {
    const float*  conf = (const float*)d_in[0];
    const float4* loc  = (const float4*)d_in[1];
    const void*   ct   = d_in[2];
    const float4* loct = (const float4*)d_in[3];
    float*        out  = (float*)d_out;
    (void)in_sizes; (void)n_in;

    k_detect<<<8, 256>>>((const int2*)ct);
    k_main<<<GRID_MAIN, TPB>>>(conf, loc, ct, loct, out, out_size);
}